// round 8
// baseline (speedup 1.0000x reference)
#include <cuda_runtime.h>
#include <math.h>

// QuantumPoolingLayer R8: contiguous-stream pool (unchanged, ~6.98 TB/s) +
// warp-cooperative sim: 32 lanes/warp share widx -> gate matrices computed
// once per warp (24 sincos spread over lanes), per-thread chain is FMA-only.

#define NQ 4

__device__ float g_part[64 * 16 * 2 * 512];   // [b][rg][ch][m] partial sums (4 MB)

struct c32 { float x, y; };
__device__ __forceinline__ c32 cadd(c32 a, c32 b){ return {a.x+b.x, a.y+b.y}; }
__device__ __forceinline__ c32 cmul(c32 a, c32 b){
    return { fmaf(a.x, b.x, -a.y*b.y), fmaf(a.x, b.y, a.y*b.x) };
}

// K1: grid (rg=16, b=64), 512 threads, 2 blocks/SM.
// Block streams rows [rg*4, rg*4+4), all j, all m: 256 KB CONTIGUOUS.
// Thread: ml = tid&127 (float4 over m), p = tid>>7 covers j ≡ p (mod 4).
__global__ void __launch_bounds__(512, 2)
pool_kernel(const float* __restrict__ in)
{
    const int rg = blockIdx.x;           // 4-row group, 0..15
    const int b  = blockIdx.y;
    const int tid = threadIdx.x;
    const int ml  = tid & 127;           // m float4 lane
    const int p   = tid >> 7;            // 0..3

    const float* tb = in
        + ((size_t)(b * 64 + rg * 4) * 64) * 512   // start of the 4-row span
        + (size_t)p * 512 + (ml << 2);

    float4 acc0 = {0.f,0.f,0.f,0.f};     // colhalf 0 (j < 32)
    float4 acc1 = {0.f,0.f,0.f,0.f};     // colhalf 1 (j >= 32)

#pragma unroll
    for (int il = 0; il < 4; il++) {
        const float* rbase = tb + (size_t)il * 64 * 512;
        {
            float4 v[8];
#pragma unroll
            for (int k = 0; k < 8; k++)
                v[k] = __ldcs(reinterpret_cast<const float4*>(rbase + (size_t)k * 2048));
#pragma unroll
            for (int k = 0; k < 8; k++) {
                acc0.x += v[k].x; acc0.y += v[k].y; acc0.z += v[k].z; acc0.w += v[k].w;
            }
        }
        {
            float4 v[8];
#pragma unroll
            for (int k = 0; k < 8; k++)
                v[k] = __ldcs(reinterpret_cast<const float4*>(rbase + (size_t)(k + 8) * 2048));
#pragma unroll
            for (int k = 0; k < 8; k++) {
                acc1.x += v[k].x; acc1.y += v[k].y; acc1.z += v[k].z; acc1.w += v[k].w;
            }
        }
    }

    __shared__ float4 part[4][2][128];   // [p][ch][ml], 16 KB
    part[p][0][ml] = acc0;
    part[p][1][ml] = acc1;
    __syncthreads();

    if (tid < 256) {
        const int ch  = tid >> 7;
        const int mlr = tid & 127;
        float4 ssum = {0.f,0.f,0.f,0.f};
#pragma unroll
        for (int q = 0; q < 4; q++) {
            float4 v = part[q][ch][mlr];
            ssum.x += v.x; ssum.y += v.y; ssum.z += v.z; ssum.w += v.w;
        }
        float4* dst = reinterpret_cast<float4*>(g_part) +
                      (size_t)(((b * 16 + rg) * 2 + ch) * 128 + mlr);
        *dst = ssum;
    }
}

// K2: one thread per sample, 512 blocks x 64 threads. Warp shares widx:
// gate table built cooperatively, then per-thread FMA-only circuit.
__global__ void __launch_bounds__(64)
sim_kernel(const float* __restrict__ w, float* __restrict__ out)
{
    const int n    = blockIdx.x * 64 + threadIdx.x;  // sample = b*512 + m
    const int lane = threadIdx.x & 31;
    const int wrp  = threadIdx.x >> 5;
    const int b = n >> 9;
    const int m = n & 511;

    // --- scratch combine: issue independent loads first ---
    float quad[4] = {0.f, 0.f, 0.f, 0.f};
#pragma unroll
    for (int rg = 0; rg < 16; rg++) {
        const int rh = rg >> 3;
        quad[rh * 2 + 0] += g_part[(size_t)(((b * 16 + rg) * 2 + 0) * 512 + m)];
        quad[rh * 2 + 1] += g_part[(size_t)(((b * 16 + rg) * 2 + 1) * 512 + m)];
    }

    // --- warp-cooperative gate table (widx = n>>6 uniform across warp) ---
    __shared__ float sc[2][8][3][2];     // [warp][gate][comp][sin,cos]
    __shared__ float gt[2][8][4];        // [warp][gate][A,B,C,D]
    const float* wp = w + (size_t)(n >> 6) * 24;
    if (lane < 24) {
        const int g = lane / 3, c = lane - g * 3;
        float phi = wp[g * 3 + 0], th = wp[g * 3 + 1], om = wp[g * 3 + 2];
        float arg = (c == 0) ? 0.5f * th
                  : (c == 1) ? 0.5f * (phi + om)
                             : 0.5f * (phi - om);
        float sn, cs; __sincosf(arg, &sn, &cs);
        sc[wrp][g][c][0] = sn; sc[wrp][g][c][1] = cs;
    }
    __syncwarp();
    if (lane < 8) {
        const int g = lane;
        float stt = sc[wrp][g][0][0], ctt = sc[wrp][g][0][1];
        float sa  = sc[wrp][g][1][0], ca  = sc[wrp][g][1][1];
        float sb  = sc[wrp][g][2][0], cb  = sc[wrp][g][2][1];
        gt[wrp][g][0] = ctt * ca;   // A
        gt[wrp][g][1] = ctt * sa;   // B
        gt[wrp][g][2] = stt * cb;   // C
        gt[wrp][g][3] = stt * sb;   // D
    }
    __syncwarp();

    float x[4];
#pragma unroll
    for (int q = 0; q < 4; q++)
        x[q] = tanhf(quad[q] * (1.0f / 1024.0f));

    // --- circuit ---
    c32 s[16];
#pragma unroll
    for (int k = 0; k < 16; k++) s[k] = {0.f, 0.f};
    s[0].x = 1.f;

    // Initial RY(x*pi); wire q <-> bit (3-q) => mask = 8>>q.
#pragma unroll
    for (int q = 0; q < NQ; q++) {
        float half = x[q] * 1.57079632679489662f;
        float sn, cs; __sincosf(half, &sn, &cs);
        const int mk = 8 >> q;
#pragma unroll
        for (int k = 0; k < 16; k++) {
            if (!(k & mk)) {
                c32 v0 = s[k], v1 = s[k | mk];
                s[k]      = { cs*v0.x - sn*v1.x, cs*v0.y - sn*v1.y };
                s[k | mk] = { sn*v0.x + cs*v1.x, sn*v0.y + cs*v1.y };
            }
        }
    }

#pragma unroll
    for (int layer = 0; layer < 2; layer++) {
#pragma unroll
        for (int q = 0; q < NQ; q++) {
            const float* G = gt[wrp][layer * 4 + q];
            const float A = G[0], B = G[1], C = G[2], D = G[3];
            c32 U00 = {  A, -B };
            c32 U01 = { -C, -D };
            c32 U10 = {  C, -D };
            c32 U11 = {  A,  B };
            const int mk = 8 >> q;
#pragma unroll
            for (int k = 0; k < 16; k++) {
                if (!(k & mk)) {
                    c32 v0 = s[k], v1 = s[k | mk];
                    c32 n0 = cadd(cmul(U00, v0), cmul(U01, v1));
                    c32 n1 = cadd(cmul(U10, v0), cmul(U11, v1));
                    s[k] = n0; s[k | mk] = n1;
                }
            }
        }
        // CNOT(c,t) for all c<t in order: amplitude swaps.
#pragma unroll
        for (int c = 0; c < NQ; c++) {
#pragma unroll
            for (int t = c + 1; t < NQ; t++) {
                const int cm = 8 >> c, tm = 8 >> t;
#pragma unroll
                for (int k = 0; k < 16; k++) {
                    if ((k & cm) && !(k & tm)) {
                        c32 tmp = s[k]; s[k] = s[k | tm]; s[k | tm] = tmp;
                    }
                }
            }
        }
    }

    float p = 0.f;
#pragma unroll
    for (int k = 0; k < 16; k++) {
        float pr = fmaf(s[k].x, s[k].x, s[k].y * s[k].y);
        p += (k < 8) ? pr : -pr;
    }
    out[n] = p;
}

extern "C" void kernel_launch(void* const* d_in, const int* in_sizes, int n_in,
                              void* d_out, int out_size)
{
    const float* in = (const float*)d_in[0];
    const float* w  = (const float*)d_in[1];
    if (n_in >= 2 && in_sizes[0] < in_sizes[1]) {   // defensive: identify by size
        in = (const float*)d_in[1];
        w  = (const float*)d_in[0];
    }
    dim3 grid1(16, 64);
    pool_kernel<<<grid1, 512>>>(in);
    sim_kernel<<<512, 64>>>(w, (float*)d_out);
}

// round 9
// speedup vs baseline: 1.0510x; 1.0510x over previous
#include <cuda_runtime.h>
#include <math.h>

// QuantumPoolingLayer R9: contiguous-stream pool at 256 KiB granularity
// (2048 blocks, 6.9 waves -> straggle halved) + warp-cooperative sim.
// Scratch: float2 {colhalf0, colhalf1} per (b, 2-row-group, m), 8 MB.

#define NQ 4

__device__ float2 g_part[64 * 32 * 512];   // [b][rg][m] -> (ch0, ch1) partials

struct c32 { float x, y; };
__device__ __forceinline__ c32 cadd(c32 a, c32 b){ return {a.x+b.x, a.y+b.y}; }
__device__ __forceinline__ c32 cmul(c32 a, c32 b){
    return { fmaf(a.x, b.x, -a.y*b.y), fmaf(a.x, b.y, a.y*b.x) };
}

// K1: grid (rg=32, b=64), 512 threads, 2 blocks/SM.
// Block streams rows [rg*2, rg*2+2), all j, all m: 256 KB CONTIGUOUS.
// Thread: ml = tid&127 (float4 over m), p = tid>>7 covers j ≡ p (mod 4).
__global__ void __launch_bounds__(512, 2)
pool_kernel(const float* __restrict__ in)
{
    const int rg = blockIdx.x;           // 2-row group, 0..31
    const int b  = blockIdx.y;
    const int tid = threadIdx.x;
    const int ml  = tid & 127;           // m float4 lane
    const int p   = tid >> 7;            // 0..3

    const float* tb = in
        + ((size_t)(b * 64 + rg * 2) * 64) * 512   // start of the 2-row span
        + (size_t)p * 512 + (ml << 2);

    float4 acc0 = {0.f,0.f,0.f,0.f};     // colhalf 0 (j < 32)
    float4 acc1 = {0.f,0.f,0.f,0.f};     // colhalf 1 (j >= 32)

#pragma unroll
    for (int il = 0; il < 2; il++) {
        const float* rbase = tb + (size_t)il * 64 * 512;
        {
            float4 v[8];
#pragma unroll
            for (int k = 0; k < 8; k++)
                v[k] = __ldcs(reinterpret_cast<const float4*>(rbase + (size_t)k * 2048));
#pragma unroll
            for (int k = 0; k < 8; k++) {
                acc0.x += v[k].x; acc0.y += v[k].y; acc0.z += v[k].z; acc0.w += v[k].w;
            }
        }
        {
            float4 v[8];
#pragma unroll
            for (int k = 0; k < 8; k++)
                v[k] = __ldcs(reinterpret_cast<const float4*>(rbase + (size_t)(k + 8) * 2048));
#pragma unroll
            for (int k = 0; k < 8; k++) {
                acc1.x += v[k].x; acc1.y += v[k].y; acc1.z += v[k].z; acc1.w += v[k].w;
            }
        }
    }

    __shared__ float part[4][2][512];    // [p][ch][m], 16 KB
    reinterpret_cast<float4*>(part[p][0])[ml] = acc0;
    reinterpret_cast<float4*>(part[p][1])[ml] = acc1;
    __syncthreads();

    // tid = m: reduce over p for both col halves, write packed float2.
    {
        float s0 = part[0][0][tid] + part[1][0][tid] + part[2][0][tid] + part[3][0][tid];
        float s1 = part[0][1][tid] + part[1][1][tid] + part[2][1][tid] + part[3][1][tid];
        g_part[(size_t)(b * 32 + rg) * 512 + tid] = make_float2(s0, s1);
    }
}

// K2: one thread per sample, 512 blocks x 64 threads. Warp shares widx:
// gate table built cooperatively, then per-thread FMA-only circuit.
__global__ void __launch_bounds__(64)
sim_kernel(const float* __restrict__ w, float* __restrict__ out)
{
    const int n    = blockIdx.x * 64 + threadIdx.x;  // sample = b*512 + m
    const int lane = threadIdx.x & 31;
    const int wrp  = threadIdx.x >> 5;
    const int b = n >> 9;
    const int m = n & 511;

    // --- scratch combine: 32 coalesced float2 loads, independent ---
    float quad[4] = {0.f, 0.f, 0.f, 0.f};
#pragma unroll
    for (int rg = 0; rg < 32; rg++) {
        float2 v = g_part[(size_t)(b * 32 + rg) * 512 + m];
        const int rh = rg >> 4;          // rows [rg*2, rg*2+2) -> half
        quad[rh * 2 + 0] += v.x;
        quad[rh * 2 + 1] += v.y;
    }

    // --- warp-cooperative gate table (widx = n>>6 uniform across warp) ---
    __shared__ float sc[2][8][3][2];     // [warp][gate][comp][sin,cos]
    __shared__ float gt[2][8][4];        // [warp][gate][A,B,C,D]
    const float* wp = w + (size_t)(n >> 6) * 24;
    if (lane < 24) {
        const int g = lane / 3, c = lane - g * 3;
        float phi = wp[g * 3 + 0], th = wp[g * 3 + 1], om = wp[g * 3 + 2];
        float arg = (c == 0) ? 0.5f * th
                  : (c == 1) ? 0.5f * (phi + om)
                             : 0.5f * (phi - om);
        float sn, cs; __sincosf(arg, &sn, &cs);
        sc[wrp][g][c][0] = sn; sc[wrp][g][c][1] = cs;
    }
    __syncwarp();
    if (lane < 8) {
        const int g = lane;
        float stt = sc[wrp][g][0][0], ctt = sc[wrp][g][0][1];
        float sa  = sc[wrp][g][1][0], ca  = sc[wrp][g][1][1];
        float sb  = sc[wrp][g][2][0], cb  = sc[wrp][g][2][1];
        gt[wrp][g][0] = ctt * ca;   // A
        gt[wrp][g][1] = ctt * sa;   // B
        gt[wrp][g][2] = stt * cb;   // C
        gt[wrp][g][3] = stt * sb;   // D
    }
    __syncwarp();

    float x[4];
#pragma unroll
    for (int q = 0; q < 4; q++)
        x[q] = tanhf(quad[q] * (1.0f / 1024.0f));

    // --- circuit ---
    c32 s[16];
#pragma unroll
    for (int k = 0; k < 16; k++) s[k] = {0.f, 0.f};
    s[0].x = 1.f;

    // Initial RY(x*pi); wire q <-> bit (3-q) => mask = 8>>q.
#pragma unroll
    for (int q = 0; q < NQ; q++) {
        float half = x[q] * 1.57079632679489662f;
        float sn, cs; __sincosf(half, &sn, &cs);
        const int mk = 8 >> q;
#pragma unroll
        for (int k = 0; k < 16; k++) {
            if (!(k & mk)) {
                c32 v0 = s[k], v1 = s[k | mk];
                s[k]      = { cs*v0.x - sn*v1.x, cs*v0.y - sn*v1.y };
                s[k | mk] = { sn*v0.x + cs*v1.x, sn*v0.y + cs*v1.y };
            }
        }
    }

#pragma unroll
    for (int layer = 0; layer < 2; layer++) {
#pragma unroll
        for (int q = 0; q < NQ; q++) {
            const float* G = gt[wrp][layer * 4 + q];
            const float A = G[0], B = G[1], C = G[2], D = G[3];
            c32 U00 = {  A, -B };
            c32 U01 = { -C, -D };
            c32 U10 = {  C, -D };
            c32 U11 = {  A,  B };
            const int mk = 8 >> q;
#pragma unroll
            for (int k = 0; k < 16; k++) {
                if (!(k & mk)) {
                    c32 v0 = s[k], v1 = s[k | mk];
                    c32 n0 = cadd(cmul(U00, v0), cmul(U01, v1));
                    c32 n1 = cadd(cmul(U10, v0), cmul(U11, v1));
                    s[k] = n0; s[k | mk] = n1;
                }
            }
        }
        // CNOT(c,t) for all c<t in order: amplitude swaps.
#pragma unroll
        for (int c = 0; c < NQ; c++) {
#pragma unroll
            for (int t = c + 1; t < NQ; t++) {
                const int cm = 8 >> c, tm = 8 >> t;
#pragma unroll
                for (int k = 0; k < 16; k++) {
                    if ((k & cm) && !(k & tm)) {
                        c32 tmp = s[k]; s[k] = s[k | tm]; s[k | tm] = tmp;
                    }
                }
            }
        }
    }

    float p = 0.f;
#pragma unroll
    for (int k = 0; k < 16; k++) {
        float pr = fmaf(s[k].x, s[k].x, s[k].y * s[k].y);
        p += (k < 8) ? pr : -pr;
    }
    out[n] = p;
}

extern "C" void kernel_launch(void* const* d_in, const int* in_sizes, int n_in,
                              void* d_out, int out_size)
{
    const float* in = (const float*)d_in[0];
    const float* w  = (const float*)d_in[1];
    if (n_in >= 2 && in_sizes[0] < in_sizes[1]) {   // defensive: identify by size
        in = (const float*)d_in[1];
        w  = (const float*)d_in[0];
    }
    dim3 grid1(32, 64);
    pool_kernel<<<grid1, 512>>>(in);
    sim_kernel<<<512, 64>>>(w, (float*)d_out);
}